// round 9
// baseline (speedup 1.0000x reference)
#include <cuda_runtime.h>
#include <cuda_bf16.h>
#include <cstddef>
#include <cstdint>

#define N_NODES 30000
#define E_EDGES 480000
#define HID 256
#define HEADS 8
#define NLAYERS 6
#define NODE_IN 13
#define EDGE_IN 10

// ---------------- static device scratch (no allocations allowed) ----------------
__device__ float g_h   [N_NODES * HID];
__device__ float g_xl  [N_NODES * HID];
__device__ float g_xr  [N_NODES * HID];
__device__ float g_mlp [N_NODES * 128];
__device__ float g_V   [NLAYERS * 11 * HID];   // rows 0..9: edge_attr coeffs; row 10: const
__device__ int   g_deg [N_NODES];
__device__ int   g_rowoff[N_NODES + 1];
__device__ int   g_cursor[N_NODES];
__device__ int   g_perm[E_EDGES];

// ---------------- CSR build ----------------
__global__ void zero_int_kernel(int* p, int n) {
    int i = blockIdx.x * blockDim.x + threadIdx.x;
    if (i < n) p[i] = 0;
}

__global__ void count_kernel(const int* __restrict__ dst, int* __restrict__ deg) {
    int e = blockIdx.x * blockDim.x + threadIdx.x;
    if (e < E_EDGES) atomicAdd(&deg[dst[e]], 1);
}

__global__ void scan_kernel(const int* __restrict__ deg, int* __restrict__ rowoff,
                            int* __restrict__ cursor) {
    __shared__ int s[1024];
    int tid = threadIdx.x;
    const int CH = (N_NODES + 1023) / 1024;  // 30
    int base = tid * CH;
    int sum = 0;
    for (int i = 0; i < CH; i++) {
        int idx = base + i;
        if (idx < N_NODES) sum += deg[idx];
    }
    s[tid] = sum;
    __syncthreads();
    for (int off = 1; off < 1024; off <<= 1) {
        int v = (tid >= off) ? s[tid - off] : 0;
        __syncthreads();
        s[tid] += v;
        __syncthreads();
    }
    int run = s[tid] - sum;  // exclusive prefix
    for (int i = 0; i < CH; i++) {
        int idx = base + i;
        if (idx < N_NODES) {
            rowoff[idx] = run;
            cursor[idx] = run;
            run += deg[idx];
        }
    }
    if (tid == 1023) rowoff[N_NODES] = run;
}

__global__ void scatter_kernel(const int* __restrict__ dst, int* __restrict__ cursor,
                               int* __restrict__ perm) {
    int e = blockIdx.x * blockDim.x + threadIdx.x;
    if (e < E_EDGES) {
        int p = atomicAdd(&cursor[dst[e]], 1);
        perm[p] = e;
    }
}

// ---------------- node input projection ----------------
__global__ void node_in_kernel(const float* __restrict__ x, const float* __restrict__ W,
                               const float* __restrict__ b, float* __restrict__ h) {
    int idx = blockIdx.x * blockDim.x + threadIdx.x;
    if (idx >= N_NODES * HID) return;
    int r = idx >> 8, c = idx & 255;
    float s = b[c];
#pragma unroll
    for (int k = 0; k < NODE_IN; k++) s += x[r * NODE_IN + k] * W[k * HID + c];
    h[idx] = s;
}

// ---------------- edge-chain collapse: V_l = Uaug_l @ We_l, Uaug_{l+1} = Uaug_l @ Weu_l (+beu) ----------------
__global__ void precompute_V_kernel(const float* __restrict__ edge_W, const float* __restrict__ edge_b,
                                    const float* __restrict__ We, const float* __restrict__ Weu,
                                    const float* __restrict__ beu, float* __restrict__ V) {
    __shared__ float U[11][HID];
    int c = threadIdx.x;  // 0..255
    for (int k = 0; k < EDGE_IN; k++) U[k][c] = edge_W[k * HID + c];
    U[10][c] = edge_b[c];
    __syncthreads();
    for (int l = 0; l < NLAYERS; l++) {
        const float* WeL  = We  + (size_t)l * HID * HID;
        const float* WeuL = Weu + (size_t)l * HID * HID;
        float accV[11], accU[11];
#pragma unroll
        for (int k = 0; k < 11; k++) { accV[k] = 0.f; accU[k] = 0.f; }
        for (int j = 0; j < HID; j++) {
            float we  = WeL [j * HID + c];
            float weu = WeuL[j * HID + c];
#pragma unroll
            for (int k = 0; k < 11; k++) {
                float u = U[k][j];
                accV[k] += u * we;
                accU[k] += u * weu;
            }
        }
        accU[10] += beu[l * HID + c];
#pragma unroll
        for (int k = 0; k < 11; k++) V[((size_t)l * 11 + k) * HID + c] = accV[k];
        __syncthreads();
#pragma unroll
        for (int k = 0; k < 11; k++) U[k][c] = accU[k];
        __syncthreads();
    }
}

// ---------------- 3xTF32 tensor-core GEMM (near-fp32 accuracy) ----------------
// Dual-B variant: grid.x in [0, 2*nColBlk); blocks with bx < nColBlk use B1/bias1/C1,
// others B2/bias2/C2. Inner loop identical to the verified 3xTF32 kernel.
#define BM 128
#define BN 128
#define BK 16
#define AS_STRIDE 20
#define BS_STRIDE 136

__device__ __forceinline__ uint32_t f2tf(float f) {
    uint32_t u;
    asm("cvt.rna.tf32.f32 %0, %1;" : "=r"(u) : "f"(f));
    return u;
}

__device__ __forceinline__ void mma_tf32(float* c, const uint32_t* a, uint32_t b0, uint32_t b1) {
    asm("mma.sync.aligned.m16n8k8.row.col.f32.tf32.tf32.f32 "
        "{%0,%1,%2,%3},{%4,%5,%6,%7},{%8,%9},{%0,%1,%2,%3};"
        : "+f"(c[0]), "+f"(c[1]), "+f"(c[2]), "+f"(c[3])
        : "r"(a[0]), "r"(a[1]), "r"(a[2]), "r"(a[3]), "r"(b0), "r"(b1));
}

__device__ __forceinline__ void split_tf(float f, uint32_t& hi, uint32_t& lo) {
    hi = f2tf(f);
    lo = f2tf(f - __uint_as_float(hi));
}

__global__ __launch_bounds__(256, 2)
void gemm_tf32x3_kernel(const float* __restrict__ A,
                        const float* __restrict__ B1, const float* __restrict__ B2,
                        const float* __restrict__ bias1, const float* __restrict__ bias2,
                        float* __restrict__ C1, float* __restrict__ C2,
                        int M, int K, int Nc, int nColBlk, int act) {
    __shared__ uint32_t AsH[BM * AS_STRIDE], AsL[BM * AS_STRIDE];
    __shared__ uint32_t BsH[BK * BS_STRIDE], BsL[BK * BS_STRIDE];

    int bx = blockIdx.x;
    const float* B    = (bx < nColBlk) ? B1 : B2;
    const float* bias = (bx < nColBlk) ? bias1 : bias2;
    float* C          = (bx < nColBlk) ? C1 : C2;
    int colBase = ((bx < nColBlk) ? bx : bx - nColBlk) * BN;

    int tid = threadIdx.x;
    int lane = tid & 31, warp = tid >> 5;
    int warpM = warp & 3, warpN = warp >> 2;  // 4 x 2
    int rowBase = blockIdx.y * BM;
    int gid = lane >> 2, tig = lane & 3;

    float acc[2][8][4];
#pragma unroll
    for (int mt = 0; mt < 2; mt++)
#pragma unroll
        for (int nt = 0; nt < 8; nt++)
#pragma unroll
            for (int i = 0; i < 4; i++) acc[mt][nt][i] = 0.f;

    for (int k0 = 0; k0 < K; k0 += BK) {
        // stage A [128 x 16]
#pragma unroll
        for (int i = 0; i < 2; i++) {
            int idx = tid + i * 256;
            int row = idx >> 2, q = idx & 3;
            int gr = rowBase + row;
            float4 v = make_float4(0.f, 0.f, 0.f, 0.f);
            if (gr < M) v = *(const float4*)(A + (size_t)gr * K + k0 + q * 4);
            uint32_t h0, l0, h1, l1, h2, l2, h3, l3;
            split_tf(v.x, h0, l0); split_tf(v.y, h1, l1);
            split_tf(v.z, h2, l2); split_tf(v.w, h3, l3);
            uint32_t* ph = &AsH[row * AS_STRIDE + q * 4];
            uint32_t* pl = &AsL[row * AS_STRIDE + q * 4];
            ph[0] = h0; ph[1] = h1; ph[2] = h2; ph[3] = h3;
            pl[0] = l0; pl[1] = l1; pl[2] = l2; pl[3] = l3;
        }
        // stage B [16 x 128]
#pragma unroll
        for (int i = 0; i < 2; i++) {
            int idx = tid + i * 256;
            int row = idx >> 5, q = idx & 31;
            float4 v = *(const float4*)(B + (size_t)(k0 + row) * Nc + colBase + q * 4);
            uint32_t h0, l0, h1, l1, h2, l2, h3, l3;
            split_tf(v.x, h0, l0); split_tf(v.y, h1, l1);
            split_tf(v.z, h2, l2); split_tf(v.w, h3, l3);
            uint32_t* ph = &BsH[row * BS_STRIDE + q * 4];
            uint32_t* pl = &BsL[row * BS_STRIDE + q * 4];
            ph[0] = h0; ph[1] = h1; ph[2] = h2; ph[3] = h3;
            pl[0] = l0; pl[1] = l1; pl[2] = l2; pl[3] = l3;
        }
        __syncthreads();

#pragma unroll
        for (int kk = 0; kk < 2; kk++) {
            int ko = kk * 8;
            uint32_t afh[2][4], afl[2][4];
#pragma unroll
            for (int mt = 0; mt < 2; mt++) {
                int r = warpM * 32 + mt * 16 + gid;
                afh[mt][0] = AsH[r * AS_STRIDE + ko + tig];
                afh[mt][1] = AsH[(r + 8) * AS_STRIDE + ko + tig];
                afh[mt][2] = AsH[r * AS_STRIDE + ko + tig + 4];
                afh[mt][3] = AsH[(r + 8) * AS_STRIDE + ko + tig + 4];
                afl[mt][0] = AsL[r * AS_STRIDE + ko + tig];
                afl[mt][1] = AsL[(r + 8) * AS_STRIDE + ko + tig];
                afl[mt][2] = AsL[r * AS_STRIDE + ko + tig + 4];
                afl[mt][3] = AsL[(r + 8) * AS_STRIDE + ko + tig + 4];
            }
#pragma unroll
            for (int nt = 0; nt < 8; nt++) {
                int n = warpN * 64 + nt * 8 + gid;
                uint32_t bh0 = BsH[(ko + tig) * BS_STRIDE + n];
                uint32_t bh1 = BsH[(ko + tig + 4) * BS_STRIDE + n];
                uint32_t bl0 = BsL[(ko + tig) * BS_STRIDE + n];
                uint32_t bl1 = BsL[(ko + tig + 4) * BS_STRIDE + n];
#pragma unroll
                for (int mt = 0; mt < 2; mt++) {
                    mma_tf32(acc[mt][nt], afh[mt], bh0, bh1);  // hi*hi
                    mma_tf32(acc[mt][nt], afh[mt], bl0, bl1);  // hi*lo
                    mma_tf32(acc[mt][nt], afl[mt], bh0, bh1);  // lo*hi
                }
            }
        }
        __syncthreads();
    }

#pragma unroll
    for (int mt = 0; mt < 2; mt++) {
        int r0 = rowBase + warpM * 32 + mt * 16 + gid;
        int r1 = r0 + 8;
#pragma unroll
        for (int nt = 0; nt < 8; nt++) {
            int c0 = colBase + warpN * 64 + nt * 8 + tig * 2;
            float v0 = acc[mt][nt][0], v1 = acc[mt][nt][1];
            float v2 = acc[mt][nt][2], v3 = acc[mt][nt][3];
            if (bias) {
                float b0 = bias[c0], b1 = bias[c0 + 1];
                v0 += b0; v1 += b1; v2 += b0; v3 += b1;
            }
            if (act) {
                v0 = (v0 >= 0.f) ? v0 : 0.01f * v0;
                v1 = (v1 >= 0.f) ? v1 : 0.01f * v1;
                v2 = (v2 >= 0.f) ? v2 : 0.01f * v2;
                v3 = (v3 >= 0.f) ? v3 : 0.01f * v3;
            }
            if (r0 < M) *(float2*)(C + (size_t)r0 * Nc + c0) = make_float2(v0, v1);
            if (r1 < M) *(float2*)(C + (size_t)r1 * Nc + c0) = make_float2(v2, v3);
        }
    }
}

// ---------------- fused attention (one pass, online softmax, software-pipelined) ----------------
// One warp per destination node. ep reconstructed on the fly from V (11x256 in smem).
// Edge j+1's perm/src/xl/eattr loads are issued before edge j's compute to hide L2 latency.
__global__ __launch_bounds__(256)
void attn_kernel(const int* __restrict__ rowoff, const int* __restrict__ perm,
                 const int* __restrict__ src, const float* __restrict__ xl,
                 const float* __restrict__ xr, const float* __restrict__ eattr,
                 const float* __restrict__ V_l, const float* __restrict__ att_l,
                 const float* __restrict__ conv_b, const float* __restrict__ rm,
                 const float* __restrict__ rv, const float* __restrict__ gg,
                 const float* __restrict__ gb, float* __restrict__ h,
                 int add_res) {
    __shared__ float sV[11 * HID];
    __shared__ float satt[HID];
    int tid = threadIdx.x;
    satt[tid] = att_l[tid];
    for (int i = tid; i < 11 * HID; i += 256) sV[i] = V_l[i];
    __syncthreads();

    int warp = tid >> 5, lane = tid & 31;
    int n = blockIdx.x * 8 + warp;
    if (n >= N_NODES) return;
    int beg = rowoff[n], end = rowoff[n + 1];
    int cb = lane * 8;

    float4 xr0 = *(const float4*)(xr + (size_t)n * HID + cb);
    float4 xr1 = *(const float4*)(xr + (size_t)n * HID + cb + 4);
    float4 at0 = *(const float4*)&satt[cb];
    float4 at1 = *(const float4*)&satt[cb + 4];
    float4 vc0 = *(const float4*)&sV[10 * HID + cb];      // constant term
    float4 vc1 = *(const float4*)&sV[10 * HID + cb + 4];

    float mx = -1e30f, den = 0.f;
    float acc[8] = {0.f, 0.f, 0.f, 0.f, 0.f, 0.f, 0.f, 0.f};

    // prefetch edge 'beg'
    float4 nl0, nl1;
    float nev[EDGE_IN];
    if (beg < end) {
        int e = perm[beg];
        int s = src[e];
        const float4* pl = (const float4*)(xl + (size_t)s * HID + cb);
        nl0 = pl[0]; nl1 = pl[1];
        const float* ept = eattr + (size_t)e * EDGE_IN;
#pragma unroll
        for (int k = 0; k < EDGE_IN; k++) nev[k] = __ldg(ept + k);
    }

    for (int j = beg; j < end; j++) {
        float4 l0 = nl0, l1 = nl1;
        float ev[EDGE_IN];
#pragma unroll
        for (int k = 0; k < EDGE_IN; k++) ev[k] = nev[k];

        // issue edge j+1's loads before computing edge j
        if (j + 1 < end) {
            int e2 = perm[j + 1];
            int s2 = src[e2];
            const float4* pl2 = (const float4*)(xl + (size_t)s2 * HID + cb);
            nl0 = pl2[0]; nl1 = pl2[1];
            const float* ept2 = eattr + (size_t)e2 * EDGE_IN;
#pragma unroll
            for (int k = 0; k < EDGE_IN; k++) nev[k] = __ldg(ept2 + k);
        }

        float ep[8] = {vc0.x, vc0.y, vc0.z, vc0.w, vc1.x, vc1.y, vc1.z, vc1.w};
#pragma unroll
        for (int k = 0; k < EDGE_IN; k++) {
            float evk = ev[k];
            const float4* pv = (const float4*)&sV[k * HID + cb];
            float4 w0 = pv[0], w1 = pv[1];
            ep[0] += evk * w0.x; ep[1] += evk * w0.y; ep[2] += evk * w0.z; ep[3] += evk * w0.w;
            ep[4] += evk * w1.x; ep[5] += evk * w1.y; ep[6] += evk * w1.z; ep[7] += evk * w1.w;
        }
        float m0 = l0.x + xr0.x + ep[0];
        float m1 = l0.y + xr0.y + ep[1];
        float m2 = l0.z + xr0.z + ep[2];
        float m3 = l0.w + xr0.w + ep[3];
        float m4 = l1.x + xr1.x + ep[4];
        float m5 = l1.y + xr1.y + ep[5];
        float m6 = l1.z + xr1.z + ep[6];
        float m7 = l1.w + xr1.w + ep[7];
        m0 = (m0 >= 0.f) ? m0 : 0.2f * m0;  m1 = (m1 >= 0.f) ? m1 : 0.2f * m1;
        m2 = (m2 >= 0.f) ? m2 : 0.2f * m2;  m3 = (m3 >= 0.f) ? m3 : 0.2f * m3;
        m4 = (m4 >= 0.f) ? m4 : 0.2f * m4;  m5 = (m5 >= 0.f) ? m5 : 0.2f * m5;
        m6 = (m6 >= 0.f) ? m6 : 0.2f * m6;  m7 = (m7 >= 0.f) ? m7 : 0.2f * m7;
        float sum = m0 * at0.x + m1 * at0.y + m2 * at0.z + m3 * at0.w
                  + m4 * at1.x + m5 * at1.y + m6 * at1.z + m7 * at1.w;
        sum += __shfl_xor_sync(0xffffffffu, sum, 1);
        sum += __shfl_xor_sync(0xffffffffu, sum, 2);     // head logit in all 4 group lanes

        // online softmax update (exact rescale; exp(0)==1 when mx unchanged)
        float mnew = fmaxf(mx, sum);
        float corr = __expf(mx - mnew);
        float w = __expf(sum - mnew);
        den = den * corr + w;
        acc[0] = acc[0] * corr + w * l0.x;
        acc[1] = acc[1] * corr + w * l0.y;
        acc[2] = acc[2] * corr + w * l0.z;
        acc[3] = acc[3] * corr + w * l0.w;
        acc[4] = acc[4] * corr + w * l1.x;
        acc[5] = acc[5] * corr + w * l1.y;
        acc[6] = acc[6] * corr + w * l1.z;
        acc[7] = acc[7] * corr + w * l1.w;
        mx = mnew;
    }

    float inv = 1.0f / (den + 1e-16f);

    // epilogue: conv bias + BN + leaky + residual
#pragma unroll
    for (int k = 0; k < 8; k++) {
        int c = cb + k;
        float v = acc[k] * inv + conv_b[c];
        v = (v - rm[c]) * rsqrtf(rv[c] + 1e-5f) * gg[c] + gb[c];
        v = (v >= 0.f) ? v : 0.01f * v;
        if (add_res) v += h[(size_t)n * HID + c];
        h[(size_t)n * HID + c] = v;
    }
}

// ---------------- final projection: [N,128] @ [128,1] ----------------
__global__ void out2_kernel(const float* __restrict__ mlp, const float* __restrict__ W2,
                            const float* __restrict__ b2, float* __restrict__ out) {
    int warp = threadIdx.x >> 5, lane = threadIdx.x & 31;
    int n = blockIdx.x * 8 + warp;
    if (n >= N_NODES) return;
    float4 m = *(const float4*)(mlp + (size_t)n * 128 + lane * 4);
    float4 w = *(const float4*)(W2 + lane * 4);
    float s = m.x * w.x + m.y * w.y + m.z * w.z + m.w * w.w;
#pragma unroll
    for (int off = 16; off; off >>= 1) s += __shfl_xor_sync(0xffffffffu, s, off);
    if (lane == 0) out[n] = s + b2[0];
}

// ---------------- launcher ----------------
static float* sym_f(const void* symbol) {
    void* p = nullptr;
    cudaGetSymbolAddress(&p, symbol);
    return (float*)p;
}
static int* sym_i(const void* symbol) {
    void* p = nullptr;
    cudaGetSymbolAddress(&p, symbol);
    return (int*)p;
}

extern "C" void kernel_launch(void* const* d_in, const int* in_sizes, int n_in,
                              void* d_out, int out_size) {
    const float* x        = (const float*)d_in[0];
    const int*   ei       = (const int*)  d_in[1];
    const float* edge_attr= (const float*)d_in[2];
    const float* node_W   = (const float*)d_in[3];
    const float* node_b   = (const float*)d_in[4];
    const float* edge_W   = (const float*)d_in[5];
    const float* edge_b   = (const float*)d_in[6];
    const float* Wl       = (const float*)d_in[7];
    const float* bl       = (const float*)d_in[8];
    const float* Wr       = (const float*)d_in[9];
    const float* br       = (const float*)d_in[10];
    const float* We       = (const float*)d_in[11];
    const float* att      = (const float*)d_in[12];
    const float* conv_b   = (const float*)d_in[13];
    const float* Weu      = (const float*)d_in[14];
    const float* beu      = (const float*)d_in[15];
    const float* bn_g     = (const float*)d_in[16];
    const float* bn_b     = (const float*)d_in[17];
    const float* bn_rm    = (const float*)d_in[18];
    const float* bn_rv    = (const float*)d_in[19];
    const float* out_W1   = (const float*)d_in[20];
    const float* out_b1   = (const float*)d_in[21];
    const float* out_W2   = (const float*)d_in[22];
    const float* out_b2   = (const float*)d_in[23];
    float* out = (float*)d_out;

    float* h   = sym_f(g_h);
    float* xl  = sym_f(g_xl);
    float* xr  = sym_f(g_xr);
    float* mlp = sym_f(g_mlp);
    float* V   = sym_f(g_V);
    int* deg    = sym_i(g_deg);
    int* rowoff = sym_i(g_rowoff);
    int* cursor = sym_i(g_cursor);
    int* perm   = sym_i(g_perm);

    const int* src = ei;
    const int* dst = ei + E_EDGES;

    // CSR build
    zero_int_kernel<<<(N_NODES + 255) / 256, 256>>>(deg, N_NODES);
    count_kernel<<<(E_EDGES + 255) / 256, 256>>>(dst, deg);
    scan_kernel<<<1, 1024>>>(deg, rowoff, cursor);
    scatter_kernel<<<(E_EDGES + 255) / 256, 256>>>(dst, cursor, perm);

    // node input projection + edge-chain collapse
    node_in_kernel<<<(N_NODES * HID + 255) / 256, 256>>>(x, node_W, node_b, h);
    precompute_V_kernel<<<1, 256>>>(edge_W, edge_b, We, Weu, beu, V);

    const int nColBlk = HID / BN;                 // 2
    dim3 gNdual(2 * nColBlk, (N_NODES + BM - 1) / BM);   // (4, 235): Wl + Wr fused

    for (int i = 0; i < NLAYERS; i++) {
        const float* Wl_i  = Wl  + (size_t)i * HID * HID;
        const float* Wr_i  = Wr  + (size_t)i * HID * HID;
        const float* bl_i  = bl  + i * HID;
        const float* br_i  = br  + i * HID;
        const float* att_i = att + (size_t)i * HID;
        const float* V_i   = V   + (size_t)i * 11 * HID;

        gemm_tf32x3_kernel<<<gNdual, 256>>>(h, Wl_i, Wr_i, bl_i, br_i, xl, xr,
                                            N_NODES, HID, HID, nColBlk, 0);

        attn_kernel<<<(N_NODES + 7) / 8, 256>>>(rowoff, perm, src, xl, xr, edge_attr,
                                                V_i, att_i,
                                                conv_b + i * HID, bn_rm + i * HID,
                                                bn_rv + i * HID, bn_g + i * HID,
                                                bn_b + i * HID, h, (i >= 1) ? 1 : 0);
    }

    // output MLP: [N,256]@[256,128] + leaky
    dim3 gO(1, (N_NODES + BM - 1) / BM);
    gemm_tf32x3_kernel<<<gO, 256>>>(h, out_W1, out_W1, out_b1, out_b1, mlp, mlp,
                                    N_NODES, HID, 128, 1, 1);
    out2_kernel<<<(N_NODES + 7) / 8, 256>>>(mlp, out_W2, out_b2, out);
}